// round 10
// baseline (speedup 1.0000x reference)
#include <cuda_runtime.h>
#include <cstdint>

// Spatial correlation sampler: out[b][dy][dx][y][x] =
//   sum_c in1[b,c,y,x] * in2[b,c,y+dy-4,x+dx-4]   (zero padded), dy,dx in 0..8
//
// Round-10 (on r9): 18 warps, 2 px/thread, 27 f32x2 accumulators, cp.async
// smem pipeline, 4 channels/stage. New:
//  - QUAD buffer (121.9 KB), wait_group 2, fill lead 3 stages
//  - per-warp channel stagger (u -> (u+w)&3) to spread LDS bursts
//  - 2 base pointers per channel, constexpr LDS offsets (alu shaved)

#define CC 128
#define HH 96
#define WW 128
#define HW (HH * WW)

#define NTHR    576          // 18 warps: (xh 2) x (ri 3) x (g 3)
#define CHPS    4            // channels per stage
#define STAGES  (CC / CHPS)  // 32
#define NBUF    4
#define W2      136          // padded row: 4 + 128 + 4 floats
#define CHF     (14 * W2)    // floats per channel slab (3 in2 + 11 in1 rows)
#define BUFF    (CHPS * CHF) // floats per stage buffer
#define BUFB    (BUFF * 4)   // bytes per stage buffer
#define SMEMB   (NBUF * BUFB)
#define NCHUNK  (CHPS * 448) // 16B chunks per stage (1792)

typedef unsigned long long ull;

__device__ __forceinline__ void fma2(ull& acc, ull a, ull b) {
    asm("fma.rn.f32x2 %0, %1, %2, %0;" : "+l"(acc) : "l"(a), "l"(b));
}

// pair (lo = hi of a, hi = lo of b)
__device__ __forceinline__ ull pkmid(ull a, ull b) {
    ull r;
    asm("{ .reg .b32 al, ah, bl, bh;\n\t"
        "  mov.b64 {al, ah}, %1;\n\t"
        "  mov.b64 {bl, bh}, %2;\n\t"
        "  mov.b64 %0, {ah, bl}; }"
        : "=l"(r) : "l"(a), "l"(b));
    return r;
}

__device__ __forceinline__ float2 unpk(ull v) {
    unsigned lo, hi;
    asm("mov.b64 {%0,%1}, %2;" : "=r"(lo), "=r"(hi) : "l"(v));
    return make_float2(__uint_as_float(lo), __uint_as_float(hi));
}

__device__ __forceinline__ void cp16(uint32_t dst, const float* src) {
    asm volatile("cp.async.cg.shared.global [%0], [%1], 16;"
                 :: "r"(dst), "l"(src) : "memory");
}

__device__ __forceinline__ int clampi(int v, int lo, int hi) {
    return v < lo ? lo : (v > hi ? hi : v);
}

__global__ __launch_bounds__(NTHR, 1) void corr_kernel(
    const float* __restrict__ in1,
    const float* __restrict__ in2,
    float* __restrict__ out)
{
    // [buf(4)][ch(4)][row(14)][col(136)]; rows 0..2 = in2 (padded cols),
    // rows 3..13 = in1 (data at col offset +4 like in2)
    extern __shared__ float sm[];

    const int tid  = threadIdx.x;
    const int lane = tid & 31;
    const int w    = tid >> 5;          // 0..17
    const int xh   = w / 9;             // x half
    const int w9   = w % 9;
    const int g    = w9 % 3;            // dy group: dy = 3g..3g+2
    const int ri   = w9 / 3;            // 0..2: in2 row of the tile
    const int b    = blockIdx.y;
    const int r0   = blockIdx.x * 3 - 4;
    const int r    = r0 + ri;           // in2 row, -4..100
    const int x0   = 2 * lane + 64 * xh;

    const float rowok = (r >= 0 && r < HH) ? 1.0f : 0.0f;

    const float* p1base = in1 + (size_t)b * CC * HW;
    const float* p2base = in2 + (size_t)b * CC * HW;
    const uint32_t smb = (uint32_t)__cvta_generic_to_shared(sm);

    // ---- zero in2 pad columns: 4 bufs x 4 ch x 3 rows x 8 floats ----
    if (tid < 384) {
        const int bu = tid / 96, q = tid % 96;
        const int ch = q / 24, q2 = q % 24;
        const int rw = q2 / 8, k = q2 & 7;
        sm[(size_t)bu * BUFF + (ch * 14 + rw) * W2 + (k < 4 ? k : 128 + k)] = 0.0f;
    }

    // ---- precompute fill slots: 1792 16B chunks / 576 threads ----
    const float* ssrc[4];
    uint32_t     sdst[4];
    const int nslots = (tid < NCHUNK - 3 * NTHR) ? 4 : 3;   // 4 for tid<64
    #pragma unroll
    for (int j = 0; j < 4; j++) {
        const int n = tid + NTHR * j;
        if (n < NCHUNK) {
            const int ch = n / 448, rem = n % 448;
            const int rr = rem >> 5, k = rem & 31;
            int srow;
            const float* base;
            if (rr < 3) {
                srow = clampi(r0 + rr, 0, HH - 1);
                base = p2base;
            } else {
                srow = clampi(r0 - 4 + (rr - 3), 0, HH - 1);
                base = p1base;
            }
            ssrc[j] = base + (size_t)ch * HW + (size_t)srow * WW + (k << 2);
            sdst[j] = smb + (((ch * 14 + rr) * W2 + 4 + (k << 2)) << 2); // buf 0
        }
    }

    #define FILL(BUF, S)                                              \
        do {                                                          \
            const size_t co = (size_t)(CHPS * (S)) * HW;              \
            const uint32_t bo = (uint32_t)(BUF) * BUFB;               \
            _Pragma("unroll")                                         \
            for (int j = 0; j < 4; j++)                               \
                if (j < nslots) cp16(sdst[j] + bo, ssrc[j] + co);     \
            asm volatile("cp.async.commit_group;" ::: "memory");      \
        } while (0)

    // 27 accumulators: pair over the 2 pixels
    ull acc[3][9];
    #pragma unroll
    for (int t = 0; t < 3; t++)
        #pragma unroll
        for (int d = 0; d < 9; d++)
            acc[t][d] = 0ull;

    // compute-side smem float offsets (within one channel slab)
    const int jbase = ri + 8 - 3 * g;              // 2..10
    const int winf  = ri * W2 + x0;                // window floats x0..x0+9
    const int af0   = (3 + jbase) * W2 + 4 + x0;   // A row t=0; t -> -t*W2

    FILL(0, 0);
    FILL(1, 1);
    FILL(2, 2);

    #pragma unroll 1
    for (int s = 0; s < STAGES; s++) {
        if (s < STAGES - 2)
            asm volatile("cp.async.wait_group 2;" ::: "memory");
        else if (s == STAGES - 2)
            asm volatile("cp.async.wait_group 1;" ::: "memory");
        else
            asm volatile("cp.async.wait_group 0;" ::: "memory");
        __syncthreads();

        // fill buffer (s+3)%4: last consumed at stage s-1 (ordered by the
        // barrier above); LDGSTS overlap this stage's compute
        if (s + 3 < STAGES) FILL((s + 3) & 3, s + 3);

        const float* bufbase = sm + (s & 3) * BUFF;
        #pragma unroll
        for (int u = 0; u < CHPS; u++) {
            // per-warp channel stagger spreads LDS bursts across slabs
            const int uu = (u + w) & 3;
            const float* base = bufbase + uu * CHF;
            const float* wb = base + winf;
            const float* ab = base + af0;

            const ull u0 = *(const ull*)(wb);
            const ull u1 = *(const ull*)(wb + 2);
            const ull u2 = *(const ull*)(wb + 4);
            const ull u3 = *(const ull*)(wb + 6);
            const ull u4 = *(const ull*)(wb + 8);
            const ull A0 = *(const ull*)(ab);
            const ull A1 = *(const ull*)(ab - W2);
            const ull A2 = *(const ull*)(ab - 2 * W2);

            ull wp[9];
            wp[0] = u0;  wp[2] = u1;  wp[4] = u2;  wp[6] = u3;  wp[8] = u4;
            wp[1] = pkmid(u0, u1);
            wp[3] = pkmid(u1, u2);
            wp[5] = pkmid(u2, u3);
            wp[7] = pkmid(u3, u4);

            #pragma unroll
            for (int d = 0; d < 9; d++) {
                fma2(acc[0][d], A0, wp[d]);
                fma2(acc[1][d], A1, wp[d]);
                fma2(acc[2][d], A2, wp[d]);
            }
        }
    }
    #undef FILL

    // ---- epilogue: x-boundary zeros came free from smem pads ----
    #pragma unroll
    for (int t = 0; t < 3; t++) {
        const int y = r + 4 - (3 * g + t);
        if (y < 0 || y >= HH) continue;        // warp-uniform
        const int dy = 3 * g + t;
        #pragma unroll
        for (int d = 0; d < 9; d++) {
            const float2 v = unpk(acc[t][d]);
            float* po = out + (((((size_t)b * 9 + dy) * 9 + d) * HH + y) * WW) + x0;
            *(float2*)po = make_float2(v.x * rowok, v.y * rowok);
        }
    }
}

extern "C" void kernel_launch(void* const* d_in, const int* in_sizes, int n_in,
                              void* d_out, int out_size)
{
    const float* in1 = (const float*)d_in[0];
    const float* in2 = (const float*)d_in[1];
    float* out = (float*)d_out;

    cudaFuncSetAttribute(corr_kernel,
                         cudaFuncAttributeMaxDynamicSharedMemorySize, SMEMB);

    // blockIdx.x = r-tile (35 tiles cover r = -4..100), blockIdx.y = batch
    dim3 grid(35, 8, 1);
    corr_kernel<<<grid, NTHR, SMEMB>>>(in1, in2, out);
}

// round 11
// speedup vs baseline: 1.1355x; 1.1355x over previous
#include <cuda_runtime.h>
#include <cstdint>

// Spatial correlation sampler: out[b][dy][dx][y][x] =
//   sum_c in1[b,c,y,x] * in2[b,c,y+dy-4,x+dx-4]   (zero padded), dy,dx in 0..8
//
// Round-11: r9 pipeline (triple-buffered cp.async, 4 ch/stage, 2 px/thread,
// 27 f32x2 accumulators) but blocks split in half along x:
//   block = 9 warps (288 thr), 64-px x-tile, 43.1 KB smem, ~96 regs
//   -> TWO independent blocks per SM: decoupled barriers fill each other's
//      issue slack (the measured ~53% per-stage convergence loss).

#define CC 128
#define HH 96
#define WW 128
#define HW (HH * WW)

#define NTHR    288          // 9 warps: (ri 3) x (g 3); lane = 2 px of 64
#define CHPS    4            // channels per stage
#define STAGES  (CC / CHPS)  // 32
#define NBUF    3
#define W2H     72           // in2 smem row: 4 + 64 + 4 floats
#define W1H     64           // in1 smem row floats
#define CHFH    (3 * W2H + 11 * W1H)   // 920 floats per channel slab
#define BUFF    (CHPS * CHFH)          // 3680 floats per stage buffer
#define BUFB    (BUFF * 4)             // 14720 B
#define SMEMB   (NBUF * BUFB)          // 44160 B
#define NCHUNK  (CHPS * 227) // 16B chunks per stage: (3*17 + 11*16) * 4 = 908

typedef unsigned long long ull;

__device__ __forceinline__ void fma2(ull& acc, ull a, ull b) {
    asm("fma.rn.f32x2 %0, %1, %2, %0;" : "+l"(acc) : "l"(a), "l"(b));
}

// pair (lo = hi of a, hi = lo of b)
__device__ __forceinline__ ull pkmid(ull a, ull b) {
    ull r;
    asm("{ .reg .b32 al, ah, bl, bh;\n\t"
        "  mov.b64 {al, ah}, %1;\n\t"
        "  mov.b64 {bl, bh}, %2;\n\t"
        "  mov.b64 %0, {ah, bl}; }"
        : "=l"(r) : "l"(a), "l"(b));
    return r;
}

__device__ __forceinline__ float2 unpk(ull v) {
    unsigned lo, hi;
    asm("mov.b64 {%0,%1}, %2;" : "=r"(lo), "=r"(hi) : "l"(v));
    return make_float2(__uint_as_float(lo), __uint_as_float(hi));
}

__device__ __forceinline__ void cp16(uint32_t dst, const float* src) {
    asm volatile("cp.async.cg.shared.global [%0], [%1], 16;"
                 :: "r"(dst), "l"(src) : "memory");
}

__device__ __forceinline__ int clampi(int v, int lo, int hi) {
    return v < lo ? lo : (v > hi ? hi : v);
}

__global__ __launch_bounds__(NTHR, 2) void corr_kernel(
    const float* __restrict__ in1,
    const float* __restrict__ in2,
    float* __restrict__ out)
{
    // per-channel slab: [0,216) = 3 in2 rows x 72 (padded), [216,920) = 11 in1 rows x 64
    extern __shared__ float sm[];

    const int tid  = threadIdx.x;
    const int lane = tid & 31;
    const int w    = tid >> 5;            // 0..8
    const int g    = w % 3;               // dy group: dy = 3g..3g+2
    const int ri   = w / 3;               // 0..2: in2 row of the tile
    const int b    = blockIdx.y;
    const int r0   = blockIdx.x * 3 - 4;
    const int r    = r0 + ri;             // in2 row, -4..100
    const int xoff = blockIdx.z * 64;     // x half: 0 or 64
    const int x0g  = xoff + 2 * lane;     // global x of this thread's pixels

    const float rowok = (r >= 0 && r < HH) ? 1.0f : 0.0f;
    const int   lhalf = (xoff == 0);      // left half -> left pad chunk invalid

    const float* p1base = in1 + (size_t)b * CC * HW;
    const float* p2base = in2 + (size_t)b * CC * HW;
    const uint32_t smb = (uint32_t)__cvta_generic_to_shared(sm);

    // ---- zero the single invalid pad chunk of each in2 row (once):
    //      3 bufs x 4 ch x 3 rows x 4 floats = 144 floats ----
    if (tid < 144) {
        const int bu = tid / 48, q = tid % 48;
        const int ch = q / 12, q2 = q % 12;
        const int rr = q2 / 4, f = q2 & 3;
        sm[(size_t)bu * BUFF + ch * CHFH + rr * W2H + (lhalf ? f : 68 + f)] = 0.0f;
    }

    // ---- precompute fill slots: 908 16B chunks / 288 threads (<=4 each) ----
    const float* ssrc[4];
    uint32_t     sdst[4];
    const int nslots = (tid < NCHUNK - 3 * NTHR) ? 4 : 3;   // 4 for tid<44
    #pragma unroll
    for (int j = 0; j < 4; j++) {
        const int n = tid + NTHR * j;
        if (n < NCHUNK) {
            const int ch = n / 227, rem = n % 227;
            if (rem < 51) {               // in2: 3 rows x 17 valid chunks
                const int rr = rem / 17, c = rem % 17;
                const int cc = c + lhalf;             // skip invalid pad chunk
                const int srow = clampi(r0 + rr, 0, HH - 1);
                ssrc[j] = p2base + (size_t)ch * HW + (size_t)srow * WW
                          + (xoff - 4 + 4 * cc);
                sdst[j] = smb + ((ch * CHFH + rr * W2H + 4 * cc) << 2);
            } else {                      // in1: 11 rows x 16 chunks
                const int rem2 = rem - 51;
                const int rw = rem2 >> 4, k = rem2 & 15;
                const int srow = clampi(r0 - 4 + rw, 0, HH - 1);
                ssrc[j] = p1base + (size_t)ch * HW + (size_t)srow * WW
                          + (xoff + 4 * k);
                sdst[j] = smb + ((ch * CHFH + 216 + rw * W1H + 4 * k) << 2);
            }
        }
    }

    #define FILL(BUF, S)                                              \
        do {                                                          \
            const size_t co = (size_t)(CHPS * (S)) * HW;              \
            const uint32_t bo = (uint32_t)(BUF) * BUFB;               \
            _Pragma("unroll")                                         \
            for (int j = 0; j < 4; j++)                               \
                if (j < nslots) cp16(sdst[j] + bo, ssrc[j] + co);     \
            asm volatile("cp.async.commit_group;" ::: "memory");      \
        } while (0)

    // 27 accumulators: f32x2 over the 2 pixels
    ull acc[3][9];
    #pragma unroll
    for (int t = 0; t < 3; t++)
        #pragma unroll
        for (int d = 0; d < 9; d++)
            acc[t][d] = 0ull;

    // compute-side smem float offsets (within a channel slab)
    const int jbase = ri + 8 - 3 * g;                 // 2..10
    const int winf  = ri * W2H + 2 * lane;            // window floats (local)
    const int af0   = 216 + jbase * W1H + 2 * lane;   // A row t=0; t -> -W1H

    FILL(0, 0);
    FILL(1, 1);

    int bufc = 0;   // s % 3
    int buff = 2;   // (s+2) % 3

    #pragma unroll 1
    for (int s = 0; s < STAGES; s++) {
        if (s < STAGES - 1)
            asm volatile("cp.async.wait_group 1;" ::: "memory");
        else
            asm volatile("cp.async.wait_group 0;" ::: "memory");
        __syncthreads();

        // fill buffer (s+2)%3: last consumed at s-1 (ordered by the barrier
        // above); LDGSTS overlap this stage's compute
        if (s + 2 < STAGES) FILL(buff, s + 2);

        const float* bufbase = sm + bufc * BUFF;
        #pragma unroll
        for (int u = 0; u < CHPS; u++) {
            const float* base = bufbase + u * CHFH;
            const float* wb = base + winf;
            const float* ab = base + af0;

            const ull u0 = *(const ull*)(wb);
            const ull u1 = *(const ull*)(wb + 2);
            const ull u2 = *(const ull*)(wb + 4);
            const ull u3 = *(const ull*)(wb + 6);
            const ull u4 = *(const ull*)(wb + 8);
            const ull A0 = *(const ull*)(ab);
            const ull A1 = *(const ull*)(ab - W1H);
            const ull A2 = *(const ull*)(ab - 2 * W1H);

            ull wp[9];
            wp[0] = u0;  wp[2] = u1;  wp[4] = u2;  wp[6] = u3;  wp[8] = u4;
            wp[1] = pkmid(u0, u1);
            wp[3] = pkmid(u1, u2);
            wp[5] = pkmid(u2, u3);
            wp[7] = pkmid(u3, u4);

            #pragma unroll
            for (int d = 0; d < 9; d++) {
                fma2(acc[0][d], A0, wp[d]);
                fma2(acc[1][d], A1, wp[d]);
                fma2(acc[2][d], A2, wp[d]);
            }
        }

        bufc = (bufc == 2) ? 0 : bufc + 1;
        buff = (buff == 2) ? 0 : buff + 1;
    }
    #undef FILL

    // ---- epilogue: x-boundary zeros came free from smem pads ----
    #pragma unroll
    for (int t = 0; t < 3; t++) {
        const int y = r + 4 - (3 * g + t);
        if (y < 0 || y >= HH) continue;        // warp-uniform
        const int dy = 3 * g + t;
        #pragma unroll
        for (int d = 0; d < 9; d++) {
            const float2 v = unpk(acc[t][d]);
            float* po = out + (((((size_t)b * 9 + dy) * 9 + d) * HH + y) * WW) + x0g;
            *(float2*)po = make_float2(v.x * rowok, v.y * rowok);
        }
    }
}

extern "C" void kernel_launch(void* const* d_in, const int* in_sizes, int n_in,
                              void* d_out, int out_size)
{
    const float* in1 = (const float*)d_in[0];
    const float* in2 = (const float*)d_in[1];
    float* out = (float*)d_out;

    cudaFuncSetAttribute(corr_kernel,
                         cudaFuncAttributeMaxDynamicSharedMemorySize, SMEMB);

    // x = r-tile (35 tiles cover r=-4..100), y = batch, z = x-half
    dim3 grid(35, 8, 2);
    corr_kernel<<<grid, NTHR, SMEMB>>>(in1, in2, out);
}

// round 13
// speedup vs baseline: 1.2485x; 1.0995x over previous
#include <cuda_runtime.h>
#include <cstdint>

// Spatial correlation sampler: out[b][dy][dx][y][x] =
//   sum_c in1[b,c,y,x] * in2[b,c,y+dy-4,x+dx-4]   (zero padded), dy,dx in 0..8
//
// Round-13 = round-12 with the deadlock fixed: producer signals `full` via
// cp.async.mbarrier.arrive.NOINC (the default inc-variant nets zero against
// the expected count -> barrier never flips -> the r12 hang).
// Structure: 1 producer warp (cp.async fills), 9 consumer warps (LDS+FFMA2),
// per-slot full/empty mbarriers, no __syncthreads in the main loop.
// Geometry: block = 64-px x-half tile, 2 px/thread, 27 f32x2 accumulators,
// 4 channels/stage, 4 slots (57.5 KB dyn smem), 2 blocks/SM.

#define CC 128
#define HH 96
#define WW 128
#define HW (HH * WW)

#define NTHR    320          // warps 0..8 consume, warp 9 produces
#define NCW     9            // consumer warps
#define CHPS    4            // channels per stage
#define STAGES  (CC / CHPS)  // 32
#define NBUF    4
#define W2H     72           // in2 smem row: 4 + 64 + 4 floats
#define W1H     64           // in1 smem row floats
#define CHFH    (3 * W2H + 11 * W1H)   // 920 floats per channel slab
#define CHFHB   (CHFH * 4)             // 3680 B
#define BUFF    (CHPS * CHFH)          // floats per slot
#define BUFB    (BUFF * 4)             // 14720 B per slot
#define SMEMB   (NBUF * BUFB)          // 58880 B

typedef unsigned long long ull;

__device__ __forceinline__ void fma2(ull& acc, ull a, ull b) {
    asm("fma.rn.f32x2 %0, %1, %2, %0;" : "+l"(acc) : "l"(a), "l"(b));
}

__device__ __forceinline__ ull pkmid(ull a, ull b) {
    ull r;
    asm("{ .reg .b32 al, ah, bl, bh;\n\t"
        "  mov.b64 {al, ah}, %1;\n\t"
        "  mov.b64 {bl, bh}, %2;\n\t"
        "  mov.b64 %0, {ah, bl}; }"
        : "=l"(r) : "l"(a), "l"(b));
    return r;
}

__device__ __forceinline__ float2 unpk(ull v) {
    unsigned lo, hi;
    asm("mov.b64 {%0,%1}, %2;" : "=r"(lo), "=r"(hi) : "l"(v));
    return make_float2(__uint_as_float(lo), __uint_as_float(hi));
}

__device__ __forceinline__ void cp16(uint32_t dst, const float* src) {
    asm volatile("cp.async.cg.shared.global [%0], [%1], 16;"
                 :: "r"(dst), "l"(src) : "memory");
}

__device__ __forceinline__ void mbar_init(uint32_t a, uint32_t cnt) {
    asm volatile("mbarrier.init.shared.b64 [%0], %1;" :: "r"(a), "r"(cnt)
                 : "memory");
}
__device__ __forceinline__ void mbar_arrive(uint32_t a) {
    asm volatile("mbarrier.arrive.release.cta.shared::cta.b64 _, [%0];"
                 :: "r"(a) : "memory");
}
// deferred arrive that counts against the initialized expected count
__device__ __forceinline__ void cp_arrive_noinc(uint32_t a) {
    asm volatile("cp.async.mbarrier.arrive.noinc.shared::cta.b64 [%0];"
                 :: "r"(a) : "memory");
}
__device__ __forceinline__ void mbar_wait(uint32_t a, uint32_t ph) {
    uint32_t done;
    do {
        asm volatile(
            "{ .reg .pred p;\n\t"
            "mbarrier.try_wait.parity.acquire.cta.shared::cta.b64 p, [%1], %2, 0x989680;\n\t"
            "selp.b32 %0, 1, 0, p; }"
            : "=r"(done) : "r"(a), "r"(ph) : "memory");
    } while (!done);
}

__device__ __forceinline__ int clampi(int v, int lo, int hi) {
    return v < lo ? lo : (v > hi ? hi : v);
}

__global__ __launch_bounds__(NTHR, 2) void corr_kernel(
    const float* __restrict__ in1,
    const float* __restrict__ in2,
    float* __restrict__ out)
{
    extern __shared__ float sm[];
    __shared__ ull mbar[2 * NBUF];       // [0..3]=full, [4..7]=empty

    const int tid  = threadIdx.x;
    const int lane = tid & 31;
    const int w    = tid >> 5;            // 0..9
    const int b    = blockIdx.y;
    const int r0   = blockIdx.x * 3 - 4;
    const int xoff = blockIdx.z * 64;     // x half
    const int lhalf = (xoff == 0);

    const float* p1base = in1 + (size_t)b * CC * HW;
    const float* p2base = in2 + (size_t)b * CC * HW;
    const uint32_t smb  = (uint32_t)__cvta_generic_to_shared(sm);
    const uint32_t mbb  = (uint32_t)__cvta_generic_to_shared(mbar);

    // ---- init mbarriers + zero OOB pad chunks (before pipeline) ----
    if (tid < NBUF) {
        mbar_init(mbb + tid * 8, 32);                // full: 32 producer lanes
        mbar_init(mbb + (NBUF + tid) * 8, NCW * 32); // empty: 288 consumers
    }
    if (tid < 192) {   // 4 bufs x 4 ch x 3 rows x 4 floats
        const int bu = tid / 48, q = tid % 48;
        const int ch = q / 12, q2 = q % 12;
        const int rr = q2 / 4, f = q2 & 3;
        sm[(size_t)bu * BUFF + ch * CHFH + rr * W2H + (lhalf ? f : 68 + f)] = 0.0f;
    }
    __syncthreads();   // once; main loop is barrier-free

    if (w == NCW) {
        // ================= PRODUCER WARP =================
        // 227 chunks per channel: 51 in2 (3x17 valid) + 176 in1 (11x16).
        const float* srcp[8];
        uint32_t     dstb[8];          // byte offset within a channel slab
        const int nj = (lane < 3) ? 8 : 7;   // 227 = 7*32 + 3
        #pragma unroll
        for (int j = 0; j < 8; j++) {
            const int n = lane + 32 * j;
            if (n < 227) {
                if (n < 51) {
                    const int rr = n / 17, c = n % 17;
                    const int cc = c + lhalf;
                    const int srow = clampi(r0 + rr, 0, HH - 1);
                    srcp[j] = p2base + (size_t)srow * WW + (xoff - 4 + 4 * cc);
                    dstb[j] = (uint32_t)((rr * W2H + 4 * cc) << 2);
                } else {
                    const int n2 = n - 51;
                    const int rw = n2 >> 4, k = n2 & 15;
                    const int srow = clampi(r0 - 4 + rw, 0, HH - 1);
                    srcp[j] = p1base + (size_t)srow * WW + (xoff + 4 * k);
                    dstb[j] = (uint32_t)((216 + rw * W1H + 4 * k) << 2);
                }
            }
        }

        #pragma unroll 1
        for (int s = 0; s < STAGES; s++) {
            const int slot = s & 3;
            const int use  = s >> 2;
            if (use > 0)
                mbar_wait(mbb + (NBUF + slot) * 8, (use - 1) & 1);

            const uint32_t bo = smb + slot * BUFB;
            #pragma unroll
            for (int ch = 0; ch < CHPS; ch++) {
                const size_t co = (size_t)(CHPS * s + ch) * HW;
                const uint32_t bc = bo + ch * CHFHB;
                #pragma unroll
                for (int j = 0; j < 8; j++)
                    if (j < nj) cp16(bc + dstb[j], srcp[j] + co);
            }
            cp_arrive_noinc(mbb + slot * 8);   // deferred, counts vs init=32
        }
    } else {
        // ================= CONSUMER WARPS =================
        const int g  = w % 3;            // dy group: dy = 3g..3g+2
        const int ri = w / 3;            // in2 row of the tile
        const int r  = r0 + ri;
        const int x0g = xoff + 2 * lane;
        const float rowok = (r >= 0 && r < HH) ? 1.0f : 0.0f;

        const int jbase = ri + 8 - 3 * g;
        const int winf  = ri * W2H + 2 * lane;
        const int af0   = 216 + jbase * W1H + 2 * lane;

        ull acc[3][9];
        #pragma unroll
        for (int t = 0; t < 3; t++)
            #pragma unroll
            for (int d = 0; d < 9; d++)
                acc[t][d] = 0ull;

        #pragma unroll 1
        for (int s = 0; s < STAGES; s++) {
            const int slot = s & 3;
            mbar_wait(mbb + slot * 8, (s >> 2) & 1);

            const float* bufbase = sm + slot * BUFF;
            #pragma unroll
            for (int u = 0; u < CHPS; u++) {
                const float* base = bufbase + u * CHFH;
                const float* wb = base + winf;
                const float* ab = base + af0;

                const ull u0 = *(const ull*)(wb);
                const ull u1 = *(const ull*)(wb + 2);
                const ull u2 = *(const ull*)(wb + 4);
                const ull u3 = *(const ull*)(wb + 6);
                const ull u4 = *(const ull*)(wb + 8);
                const ull A0 = *(const ull*)(ab);
                const ull A1 = *(const ull*)(ab - W1H);
                const ull A2 = *(const ull*)(ab - 2 * W1H);

                ull wp[9];
                wp[0] = u0;  wp[2] = u1;  wp[4] = u2;  wp[6] = u3;  wp[8] = u4;
                wp[1] = pkmid(u0, u1);
                wp[3] = pkmid(u1, u2);
                wp[5] = pkmid(u2, u3);
                wp[7] = pkmid(u3, u4);

                #pragma unroll
                for (int d = 0; d < 9; d++) {
                    fma2(acc[0][d], A0, wp[d]);
                    fma2(acc[1][d], A1, wp[d]);
                    fma2(acc[2][d], A2, wp[d]);
                }
            }
            mbar_arrive(mbb + (NBUF + slot) * 8);   // release the slot
        }

        // ---- epilogue ----
        #pragma unroll
        for (int t = 0; t < 3; t++) {
            const int y = r + 4 - (3 * g + t);
            if (y < 0 || y >= HH) continue;        // warp-uniform
            const int dy = 3 * g + t;
            #pragma unroll
            for (int d = 0; d < 9; d++) {
                const float2 v = unpk(acc[t][d]);
                float* po = out + (((((size_t)b * 9 + dy) * 9 + d) * HH + y) * WW) + x0g;
                *(float2*)po = make_float2(v.x * rowok, v.y * rowok);
            }
        }
    }
}

extern "C" void kernel_launch(void* const* d_in, const int* in_sizes, int n_in,
                              void* d_out, int out_size)
{
    const float* in1 = (const float*)d_in[0];
    const float* in2 = (const float*)d_in[1];
    float* out = (float*)d_out;

    cudaFuncSetAttribute(corr_kernel,
                         cudaFuncAttributeMaxDynamicSharedMemorySize, SMEMB);

    // x = r-tile (35 tiles cover r=-4..100), y = batch, z = x-half
    dim3 grid(35, 8, 2);
    corr_kernel<<<grid, NTHR, SMEMB>>>(in1, in2, out);
}